// round 14
// baseline (speedup 1.0000x reference)
#include <cuda_runtime.h>

// ---------------------------------------------------------------------------
// MultiHeadAttention: out = MHA(query,key,value,mask; Wq,bq,Wk,bk,Wv,bv,Wo,bo)
// B=2, S=2048, H=16, Dk=64, D=1024. All fp32.
//
// Plan:
//   kernel 1: fused Q/K/V projection GEMMs (blockIdx.z selects matrix),
//             output written in [B,H,S,Dk] layout into __device__ scratch.
//   kernel 2: flash-attention per (b,h): 64-query blocks, online softmax
//             over 2048 keys in 64-key tiles. Output -> [B,S,D] scratch.
//   kernel 3: output projection GEMM + bias -> d_out.
// ---------------------------------------------------------------------------

#define S_LEN   2048
#define B_SZ    2
#define NH      16
#define DK      64
#define DMODEL  1024
#define MROWS   (B_SZ * S_LEN)   // 4096

// Scratch (allocation-free rule: __device__ globals)
__device__ float g_q[(size_t)B_SZ * NH * S_LEN * DK];
__device__ float g_k[(size_t)B_SZ * NH * S_LEN * DK];
__device__ float g_v[(size_t)B_SZ * NH * S_LEN * DK];
__device__ float g_att[(size_t)MROWS * DMODEL];

// ---------------------------------------------------------------------------
// SGEMM body: C[128x128] tile, BK=8, 256 threads, 8x8 register tile/thread.
// ---------------------------------------------------------------------------
__global__ __launch_bounds__(256) void gemm_qkv_kernel(
    const float* __restrict__ Xq, const float* __restrict__ Xk,
    const float* __restrict__ Xv,
    const float* __restrict__ Wq, const float* __restrict__ bq,
    const float* __restrict__ Wk, const float* __restrict__ bk,
    const float* __restrict__ Wv, const float* __restrict__ bv)
{
    const int mat = blockIdx.z;
    const float* X    = (mat == 0) ? Xq : ((mat == 1) ? Xk : Xv);
    const float* W    = (mat == 0) ? Wq : ((mat == 1) ? Wk : Wv);
    const float* bias = (mat == 0) ? bq : ((mat == 1) ? bk : bv);
    float* out        = (mat == 0) ? g_q : ((mat == 1) ? g_k : g_v);

    __shared__ __align__(16) float As[8][128];   // As[k][m] (transposed A)
    __shared__ __align__(16) float Bs[8][128];   // Bs[k][n]

    const int tid  = threadIdx.x;
    const int tx   = tid & 15;
    const int ty   = tid >> 4;
    const int row0 = blockIdx.y * 128;
    const int col0 = blockIdx.x * 128;

    const int a_r = tid >> 1;          // 0..127
    const int a_c = (tid & 1) << 2;    // 0 or 4
    const int b_r = tid >> 5;          // 0..7
    const int b_c = (tid & 31) << 2;   // 0..124

    const float* Aptr = X + (size_t)(row0 + a_r) * DMODEL + a_c;
    const float* Bptr = W + (size_t)b_r * DMODEL + col0 + b_c;

    float acc[8][8];
#pragma unroll
    for (int i = 0; i < 8; i++)
#pragma unroll
        for (int j = 0; j < 8; j++) acc[i][j] = 0.f;

    for (int k0 = 0; k0 < DMODEL; k0 += 8) {
        float4 a = *(const float4*)(Aptr + k0);
        float4 w = *(const float4*)(Bptr + (size_t)k0 * DMODEL);
        __syncthreads();
        As[a_c + 0][a_r] = a.x;
        As[a_c + 1][a_r] = a.y;
        As[a_c + 2][a_r] = a.z;
        As[a_c + 3][a_r] = a.w;
        *(float4*)&Bs[b_r][b_c] = w;
        __syncthreads();
#pragma unroll
        for (int k = 0; k < 8; k++) {
            float ar[8], br[8];
            *(float4*)&ar[0] = *(const float4*)&As[k][ty * 8];
            *(float4*)&ar[4] = *(const float4*)&As[k][ty * 8 + 4];
            *(float4*)&br[0] = *(const float4*)&Bs[k][tx * 8];
            *(float4*)&br[4] = *(const float4*)&Bs[k][tx * 8 + 4];
#pragma unroll
            for (int i = 0; i < 8; i++)
#pragma unroll
                for (int j = 0; j < 8; j++)
                    acc[i][j] = fmaf(ar[i], br[j], acc[i][j]);
        }
    }

    // write C + bias into [B,H,S,Dk] layout
#pragma unroll
    for (int i = 0; i < 8; i++) {
        const int m = row0 + ty * 8 + i;
        const int b = m >> 11;            // /2048
        const int s = m & (S_LEN - 1);
#pragma unroll
        for (int j = 0; j < 8; j++) {
            const int n = col0 + tx * 8 + j;
            const int h = n >> 6;
            const int d = n & 63;
            out[(((size_t)b * NH + h) * S_LEN + s) * DK + d] = acc[i][j] + bias[n];
        }
    }
}

__global__ __launch_bounds__(256) void gemm_out_kernel(
    const float* __restrict__ Wo, const float* __restrict__ bo,
    float* __restrict__ out)
{
    __shared__ __align__(16) float As[8][128];
    __shared__ __align__(16) float Bs[8][128];

    const int tid  = threadIdx.x;
    const int tx   = tid & 15;
    const int ty   = tid >> 4;
    const int row0 = blockIdx.y * 128;
    const int col0 = blockIdx.x * 128;

    const int a_r = tid >> 1;
    const int a_c = (tid & 1) << 2;
    const int b_r = tid >> 5;
    const int b_c = (tid & 31) << 2;

    const float* Aptr = g_att + (size_t)(row0 + a_r) * DMODEL + a_c;
    const float* Bptr = Wo + (size_t)b_r * DMODEL + col0 + b_c;

    float acc[8][8];
#pragma unroll
    for (int i = 0; i < 8; i++)
#pragma unroll
        for (int j = 0; j < 8; j++) acc[i][j] = 0.f;

    for (int k0 = 0; k0 < DMODEL; k0 += 8) {
        float4 a = *(const float4*)(Aptr + k0);
        float4 w = *(const float4*)(Bptr + (size_t)k0 * DMODEL);
        __syncthreads();
        As[a_c + 0][a_r] = a.x;
        As[a_c + 1][a_r] = a.y;
        As[a_c + 2][a_r] = a.z;
        As[a_c + 3][a_r] = a.w;
        *(float4*)&Bs[b_r][b_c] = w;
        __syncthreads();
#pragma unroll
        for (int k = 0; k < 8; k++) {
            float ar[8], br[8];
            *(float4*)&ar[0] = *(const float4*)&As[k][ty * 8];
            *(float4*)&ar[4] = *(const float4*)&As[k][ty * 8 + 4];
            *(float4*)&br[0] = *(const float4*)&Bs[k][tx * 8];
            *(float4*)&br[4] = *(const float4*)&Bs[k][tx * 8 + 4];
#pragma unroll
            for (int i = 0; i < 8; i++)
#pragma unroll
                for (int j = 0; j < 8; j++)
                    acc[i][j] = fmaf(ar[i], br[j], acc[i][j]);
        }
    }

#pragma unroll
    for (int i = 0; i < 8; i++) {
        const int m = row0 + ty * 8 + i;
#pragma unroll
        for (int j = 0; j < 8; j++) {
            const int n = col0 + tx * 8 + j;
            out[(size_t)m * DMODEL + n] = acc[i][j] + bo[n];
        }
    }
}

// ---------------------------------------------------------------------------
// Flash attention: block = 64 queries of one (b,h); online softmax over
// 2048 keys in 64-key tiles. 256 threads = 16x16; each thread owns a 4q x 4k
// score micro-tile and a 4q x 4d output micro-tile. Row stats (m, l) are
// replicated across the 16 lanes of each row group via shuffle reductions.
// ---------------------------------------------------------------------------
#define APAD 68   // padded row stride (floats) for 64-wide smem tiles

__global__ __launch_bounds__(256) void attn_kernel(const int* __restrict__ mask)
{
    extern __shared__ float sm[];
    float* Qt = sm;                 // Qt[d][q]
    float* Kt = sm + 64 * APAD;     // Kt[d][j]
    float* Vs = sm + 2 * 64 * APAD; // Vs[j][d]
    float* Pt = sm + 3 * 64 * APAD; // Pt[j][q]

    const int bh = blockIdx.y;      // 0..31
    const int b  = bh >> 4;
    const int h  = bh & 15;
    const int q0 = blockIdx.x << 6;

    const float* Qb = g_q + (size_t)bh * S_LEN * DK;
    const float* Kb = g_k + (size_t)bh * S_LEN * DK;
    const float* Vb = g_v + (size_t)bh * S_LEN * DK;
    const int*   mb = mask + b * S_LEN;

    const int tid = threadIdx.x;
    const int tx  = tid & 15;
    const int ty  = tid >> 4;

    // Load Q tile transposed: Qt[d][q] = Q[q0+q][d]
#pragma unroll
    for (int r = 0; r < 4; r++) {
        const int idx4 = r * 256 + tid;      // 0..1023
        const int q    = idx4 >> 4;
        const int d4   = (idx4 & 15) << 2;
        float4 v = *(const float4*)(Qb + (size_t)(q0 + q) * DK + d4);
        Qt[(d4 + 0) * APAD + q] = v.x;
        Qt[(d4 + 1) * APAD + q] = v.y;
        Qt[(d4 + 2) * APAD + q] = v.z;
        Qt[(d4 + 3) * APAD + q] = v.w;
    }

    float m_run[4], l_run[4], o[4][4];
#pragma unroll
    for (int i = 0; i < 4; i++) {
        m_run[i] = -3.0e38f;
        l_run[i] = 0.f;
#pragma unroll
        for (int c = 0; c < 4; c++) o[i][c] = 0.f;
    }

    for (int j0 = 0; j0 < S_LEN; j0 += 64) {
        __syncthreads();  // protect Kt/Vs/Pt from previous iteration's readers
        // Load K tile transposed + V tile row-major
#pragma unroll
        for (int r = 0; r < 4; r++) {
            const int idx4 = r * 256 + tid;
            const int j    = idx4 >> 4;
            const int d4   = (idx4 & 15) << 2;
            float4 kv = *(const float4*)(Kb + (size_t)(j0 + j) * DK + d4);
            Kt[(d4 + 0) * APAD + j] = kv.x;
            Kt[(d4 + 1) * APAD + j] = kv.y;
            Kt[(d4 + 2) * APAD + j] = kv.z;
            Kt[(d4 + 3) * APAD + j] = kv.w;
            float4 vv = *(const float4*)(Vb + (size_t)(j0 + j) * DK + d4);
            *(float4*)(Vs + j * APAD + d4) = vv;
        }
        int mk[4];
#pragma unroll
        for (int jj = 0; jj < 4; jj++) mk[jj] = mb[j0 + tx * 4 + jj];
        __syncthreads();

        // S = Q @ K^T (micro tile 4x4 per thread)
        float s[4][4];
#pragma unroll
        for (int i = 0; i < 4; i++)
#pragma unroll
            for (int jj = 0; jj < 4; jj++) s[i][jj] = 0.f;

#pragma unroll 8
        for (int d = 0; d < 64; d++) {
            float qa[4], ka[4];
            *(float4*)qa = *(const float4*)(Qt + d * APAD + (ty << 2));
            *(float4*)ka = *(const float4*)(Kt + d * APAD + (tx << 2));
#pragma unroll
            for (int i = 0; i < 4; i++)
#pragma unroll
                for (int jj = 0; jj < 4; jj++)
                    s[i][jj] = fmaf(qa[i], ka[jj], s[i][jj]);
        }

        // scale (1/sqrt(64)) and mask (replace with -1e9 where mask==0)
#pragma unroll
        for (int i = 0; i < 4; i++)
#pragma unroll
            for (int jj = 0; jj < 4; jj++)
                s[i][jj] = mk[jj] ? s[i][jj] * 0.125f : -1e9f;

        // online softmax update per query row (reduce over the 16 tx lanes)
#pragma unroll
        for (int i = 0; i < 4; i++) {
            float tmax = fmaxf(fmaxf(s[i][0], s[i][1]), fmaxf(s[i][2], s[i][3]));
#pragma unroll
            for (int w = 1; w < 16; w <<= 1)
                tmax = fmaxf(tmax, __shfl_xor_sync(0xffffffffu, tmax, w));
            const float m_new = fmaxf(m_run[i], tmax);
            const float corr  = __expf(m_run[i] - m_new);
            m_run[i] = m_new;
            l_run[i] *= corr;
#pragma unroll
            for (int c = 0; c < 4; c++) o[i][c] *= corr;
            float lsum = 0.f;
#pragma unroll
            for (int jj = 0; jj < 4; jj++) {
                const float p = __expf(s[i][jj] - m_new);
                s[i][jj] = p;
                lsum += p;
            }
#pragma unroll
            for (int w = 1; w < 16; w <<= 1)
                lsum += __shfl_xor_sync(0xffffffffu, lsum, w);
            l_run[i] += lsum;
            // store probs transposed: Pt[j][q]
#pragma unroll
            for (int jj = 0; jj < 4; jj++)
                Pt[(tx * 4 + jj) * APAD + ty * 4 + i] = s[i][jj];
        }
        __syncthreads();

        // O += P @ V  (thread owns rows 4ty.., dims 4tx..)
#pragma unroll 8
        for (int j = 0; j < 64; j++) {
            float pa[4], va[4];
            *(float4*)pa = *(const float4*)(Pt + j * APAD + (ty << 2));
            *(float4*)va = *(const float4*)(Vs + j * APAD + (tx << 2));
#pragma unroll
            for (int i = 0; i < 4; i++)
#pragma unroll
                for (int c = 0; c < 4; c++)
                    o[i][c] = fmaf(pa[i], va[c], o[i][c]);
        }
    }

    // finalize: divide by l, write into [B,S,D] scratch
#pragma unroll
    for (int i = 0; i < 4; i++) {
        const float inv = 1.0f / l_run[i];
        const int   q   = q0 + ty * 4 + i;
        float4 res = make_float4(o[i][0] * inv, o[i][1] * inv,
                                 o[i][2] * inv, o[i][3] * inv);
        *(float4*)(g_att + ((size_t)(b * S_LEN + q)) * DMODEL + h * DK + (tx << 2)) = res;
    }
}

// ---------------------------------------------------------------------------
extern "C" void kernel_launch(void* const* d_in, const int* in_sizes, int n_in,
                              void* d_out, int out_size)
{
    (void)in_sizes; (void)n_in; (void)out_size;
    const float* q   = (const float*)d_in[0];
    const float* k   = (const float*)d_in[1];
    const float* v   = (const float*)d_in[2];
    const int*   msk = (const int*)  d_in[3];
    const float* Wq  = (const float*)d_in[4];
    const float* bq  = (const float*)d_in[5];
    const float* Wk  = (const float*)d_in[6];
    const float* bk  = (const float*)d_in[7];
    const float* Wv  = (const float*)d_in[8];
    const float* bv  = (const float*)d_in[9];
    const float* Wo  = (const float*)d_in[10];
    const float* bo  = (const float*)d_in[11];
    float* out = (float*)d_out;

    const int attn_smem = 4 * 64 * APAD * (int)sizeof(float);  // 69632 B
    cudaFuncSetAttribute(attn_kernel,
                         cudaFuncAttributeMaxDynamicSharedMemorySize, attn_smem);

    dim3 gp(DMODEL / 128, MROWS / 128, 3);
    gemm_qkv_kernel<<<gp, 256>>>(q, k, v, Wq, bq, Wk, bk, Wv, bv);

    attn_kernel<<<dim3(S_LEN / 64, B_SZ * NH), 256, attn_smem>>>(msk);

    gemm_out_kernel<<<dim3(DMODEL / 128, MROWS / 128), 256>>>(Wo, bo, out);
}

// round 15
// speedup vs baseline: 1.0018x; 1.0018x over previous
#include <cuda_runtime.h>

// ---------------------------------------------------------------------------
// MultiHeadAttention: out = MHA(query,key,value,mask; Wq,bq,Wk,bk,Wv,bv,Wo,bo)
// B=2, S=2048, H=16, Dk=64, D=1024. All fp32.
//
// Plan:
//   kernel 1: fused Q/K/V projection GEMMs (blockIdx.z selects matrix),
//             output written in [B,H,S,Dk] layout into __device__ scratch.
//   kernel 2: flash-attention per (b,h): 64-query blocks, online softmax
//             over 2048 keys in 64-key tiles. Output -> [B,S,D] scratch.
//   kernel 3: output projection GEMM + bias -> d_out.
// ---------------------------------------------------------------------------

#define S_LEN   2048
#define B_SZ    2
#define NH      16
#define DK      64
#define DMODEL  1024
#define MROWS   (B_SZ * S_LEN)   // 4096

// Scratch (allocation-free rule: __device__ globals)
__device__ float g_q[(size_t)B_SZ * NH * S_LEN * DK];
__device__ float g_k[(size_t)B_SZ * NH * S_LEN * DK];
__device__ float g_v[(size_t)B_SZ * NH * S_LEN * DK];
__device__ float g_att[(size_t)MROWS * DMODEL];

// ---------------------------------------------------------------------------
// SGEMM body: C[128x128] tile, BK=8, 256 threads, 8x8 register tile/thread.
// ---------------------------------------------------------------------------
__global__ __launch_bounds__(256) void gemm_qkv_kernel(
    const float* __restrict__ Xq, const float* __restrict__ Xk,
    const float* __restrict__ Xv,
    const float* __restrict__ Wq, const float* __restrict__ bq,
    const float* __restrict__ Wk, const float* __restrict__ bk,
    const float* __restrict__ Wv, const float* __restrict__ bv)
{
    const int mat = blockIdx.z;
    const float* X    = (mat == 0) ? Xq : ((mat == 1) ? Xk : Xv);
    const float* W    = (mat == 0) ? Wq : ((mat == 1) ? Wk : Wv);
    const float* bias = (mat == 0) ? bq : ((mat == 1) ? bk : bv);
    float* out        = (mat == 0) ? g_q : ((mat == 1) ? g_k : g_v);

    __shared__ __align__(16) float As[8][128];   // As[k][m] (transposed A)
    __shared__ __align__(16) float Bs[8][128];   // Bs[k][n]

    const int tid  = threadIdx.x;
    const int tx   = tid & 15;
    const int ty   = tid >> 4;
    const int row0 = blockIdx.y * 128;
    const int col0 = blockIdx.x * 128;

    const int a_r = tid >> 1;          // 0..127
    const int a_c = (tid & 1) << 2;    // 0 or 4
    const int b_r = tid >> 5;          // 0..7
    const int b_c = (tid & 31) << 2;   // 0..124

    const float* Aptr = X + (size_t)(row0 + a_r) * DMODEL + a_c;
    const float* Bptr = W + (size_t)b_r * DMODEL + col0 + b_c;

    float acc[8][8];
#pragma unroll
    for (int i = 0; i < 8; i++)
#pragma unroll
        for (int j = 0; j < 8; j++) acc[i][j] = 0.f;

    for (int k0 = 0; k0 < DMODEL; k0 += 8) {
        float4 a = *(const float4*)(Aptr + k0);
        float4 w = *(const float4*)(Bptr + (size_t)k0 * DMODEL);
        __syncthreads();
        As[a_c + 0][a_r] = a.x;
        As[a_c + 1][a_r] = a.y;
        As[a_c + 2][a_r] = a.z;
        As[a_c + 3][a_r] = a.w;
        *(float4*)&Bs[b_r][b_c] = w;
        __syncthreads();
#pragma unroll
        for (int k = 0; k < 8; k++) {
            float ar[8], br[8];
            *(float4*)&ar[0] = *(const float4*)&As[k][ty * 8];
            *(float4*)&ar[4] = *(const float4*)&As[k][ty * 8 + 4];
            *(float4*)&br[0] = *(const float4*)&Bs[k][tx * 8];
            *(float4*)&br[4] = *(const float4*)&Bs[k][tx * 8 + 4];
#pragma unroll
            for (int i = 0; i < 8; i++)
#pragma unroll
                for (int j = 0; j < 8; j++)
                    acc[i][j] = fmaf(ar[i], br[j], acc[i][j]);
        }
    }

    // write C + bias into [B,H,S,Dk] layout
#pragma unroll
    for (int i = 0; i < 8; i++) {
        const int m = row0 + ty * 8 + i;
        const int b = m >> 11;            // /2048
        const int s = m & (S_LEN - 1);
#pragma unroll
        for (int j = 0; j < 8; j++) {
            const int n = col0 + tx * 8 + j;
            const int h = n >> 6;
            const int d = n & 63;
            out[(((size_t)b * NH + h) * S_LEN + s) * DK + d] = acc[i][j] + bias[n];
        }
    }
}

__global__ __launch_bounds__(256) void gemm_out_kernel(
    const float* __restrict__ Wo, const float* __restrict__ bo,
    float* __restrict__ out)
{
    __shared__ __align__(16) float As[8][128];
    __shared__ __align__(16) float Bs[8][128];

    const int tid  = threadIdx.x;
    const int tx   = tid & 15;
    const int ty   = tid >> 4;
    const int row0 = blockIdx.y * 128;
    const int col0 = blockIdx.x * 128;

    const int a_r = tid >> 1;
    const int a_c = (tid & 1) << 2;
    const int b_r = tid >> 5;
    const int b_c = (tid & 31) << 2;

    const float* Aptr = g_att + (size_t)(row0 + a_r) * DMODEL + a_c;
    const float* Bptr = Wo + (size_t)b_r * DMODEL + col0 + b_c;

    float acc[8][8];
#pragma unroll
    for (int i = 0; i < 8; i++)
#pragma unroll
        for (int j = 0; j < 8; j++) acc[i][j] = 0.f;

    for (int k0 = 0; k0 < DMODEL; k0 += 8) {
        float4 a = *(const float4*)(Aptr + k0);
        float4 w = *(const float4*)(Bptr + (size_t)k0 * DMODEL);
        __syncthreads();
        As[a_c + 0][a_r] = a.x;
        As[a_c + 1][a_r] = a.y;
        As[a_c + 2][a_r] = a.z;
        As[a_c + 3][a_r] = a.w;
        *(float4*)&Bs[b_r][b_c] = w;
        __syncthreads();
#pragma unroll
        for (int k = 0; k < 8; k++) {
            float ar[8], br[8];
            *(float4*)&ar[0] = *(const float4*)&As[k][ty * 8];
            *(float4*)&ar[4] = *(const float4*)&As[k][ty * 8 + 4];
            *(float4*)&br[0] = *(const float4*)&Bs[k][tx * 8];
            *(float4*)&br[4] = *(const float4*)&Bs[k][tx * 8 + 4];
#pragma unroll
            for (int i = 0; i < 8; i++)
#pragma unroll
                for (int j = 0; j < 8; j++)
                    acc[i][j] = fmaf(ar[i], br[j], acc[i][j]);
        }
    }

#pragma unroll
    for (int i = 0; i < 8; i++) {
        const int m = row0 + ty * 8 + i;
#pragma unroll
        for (int j = 0; j < 8; j++) {
            const int n = col0 + tx * 8 + j;
            out[(size_t)m * DMODEL + n] = acc[i][j] + bo[n];
        }
    }
}

// ---------------------------------------------------------------------------
// Flash attention: block = 64 queries of one (b,h); online softmax over
// 2048 keys in 64-key tiles. 256 threads = 16x16; each thread owns a 4q x 4k
// score micro-tile and a 4q x 4d output micro-tile. Row stats (m, l) are
// replicated across the 16 lanes of each row group via shuffle reductions.
// ---------------------------------------------------------------------------
#define APAD 68   // padded row stride (floats) for 64-wide smem tiles

__global__ __launch_bounds__(256) void attn_kernel(const int* __restrict__ mask)
{
    extern __shared__ float sm[];
    float* Qt = sm;                 // Qt[d][q]
    float* Kt = sm + 64 * APAD;     // Kt[d][j]
    float* Vs = sm + 2 * 64 * APAD; // Vs[j][d]
    float* Pt = sm + 3 * 64 * APAD; // Pt[j][q]

    const int bh = blockIdx.y;      // 0..31
    const int b  = bh >> 4;
    const int h  = bh & 15;
    const int q0 = blockIdx.x << 6;

    const float* Qb = g_q + (size_t)bh * S_LEN * DK;
    const float* Kb = g_k + (size_t)bh * S_LEN * DK;
    const float* Vb = g_v + (size_t)bh * S_LEN * DK;
    const int*   mb = mask + b * S_LEN;

    const int tid = threadIdx.x;
    const int tx  = tid & 15;
    const int ty  = tid >> 4;

    // Load Q tile transposed: Qt[d][q] = Q[q0+q][d]
#pragma unroll
    for (int r = 0; r < 4; r++) {
        const int idx4 = r * 256 + tid;      // 0..1023
        const int q    = idx4 >> 4;
        const int d4   = (idx4 & 15) << 2;
        float4 v = *(const float4*)(Qb + (size_t)(q0 + q) * DK + d4);
        Qt[(d4 + 0) * APAD + q] = v.x;
        Qt[(d4 + 1) * APAD + q] = v.y;
        Qt[(d4 + 2) * APAD + q] = v.z;
        Qt[(d4 + 3) * APAD + q] = v.w;
    }

    float m_run[4], l_run[4], o[4][4];
#pragma unroll
    for (int i = 0; i < 4; i++) {
        m_run[i] = -3.0e38f;
        l_run[i] = 0.f;
#pragma unroll
        for (int c = 0; c < 4; c++) o[i][c] = 0.f;
    }

    for (int j0 = 0; j0 < S_LEN; j0 += 64) {
        __syncthreads();  // protect Kt/Vs/Pt from previous iteration's readers
        // Load K tile transposed + V tile row-major
#pragma unroll
        for (int r = 0; r < 4; r++) {
            const int idx4 = r * 256 + tid;
            const int j    = idx4 >> 4;
            const int d4   = (idx4 & 15) << 2;
            float4 kv = *(const float4*)(Kb + (size_t)(j0 + j) * DK + d4);
            Kt[(d4 + 0) * APAD + j] = kv.x;
            Kt[(d4 + 1) * APAD + j] = kv.y;
            Kt[(d4 + 2) * APAD + j] = kv.z;
            Kt[(d4 + 3) * APAD + j] = kv.w;
            float4 vv = *(const float4*)(Vb + (size_t)(j0 + j) * DK + d4);
            *(float4*)(Vs + j * APAD + d4) = vv;
        }
        int mk[4];
#pragma unroll
        for (int jj = 0; jj < 4; jj++) mk[jj] = mb[j0 + tx * 4 + jj];
        __syncthreads();

        // S = Q @ K^T (micro tile 4x4 per thread)
        float s[4][4];
#pragma unroll
        for (int i = 0; i < 4; i++)
#pragma unroll
            for (int jj = 0; jj < 4; jj++) s[i][jj] = 0.f;

#pragma unroll 8
        for (int d = 0; d < 64; d++) {
            float qa[4], ka[4];
            *(float4*)qa = *(const float4*)(Qt + d * APAD + (ty << 2));
            *(float4*)ka = *(const float4*)(Kt + d * APAD + (tx << 2));
#pragma unroll
            for (int i = 0; i < 4; i++)
#pragma unroll
                for (int jj = 0; jj < 4; jj++)
                    s[i][jj] = fmaf(qa[i], ka[jj], s[i][jj]);
        }

        // scale (1/sqrt(64)) and mask (replace with -1e9 where mask==0)
#pragma unroll
        for (int i = 0; i < 4; i++)
#pragma unroll
            for (int jj = 0; jj < 4; jj++)
                s[i][jj] = mk[jj] ? s[i][jj] * 0.125f : -1e9f;

        // online softmax update per query row (reduce over the 16 tx lanes)
#pragma unroll
        for (int i = 0; i < 4; i++) {
            float tmax = fmaxf(fmaxf(s[i][0], s[i][1]), fmaxf(s[i][2], s[i][3]));
#pragma unroll
            for (int w = 1; w < 16; w <<= 1)
                tmax = fmaxf(tmax, __shfl_xor_sync(0xffffffffu, tmax, w));
            const float m_new = fmaxf(m_run[i], tmax);
            const float corr  = __expf(m_run[i] - m_new);
            m_run[i] = m_new;
            l_run[i] *= corr;
#pragma unroll
            for (int c = 0; c < 4; c++) o[i][c] *= corr;
            float lsum = 0.f;
#pragma unroll
            for (int jj = 0; jj < 4; jj++) {
                const float p = __expf(s[i][jj] - m_new);
                s[i][jj] = p;
                lsum += p;
            }
#pragma unroll
            for (int w = 1; w < 16; w <<= 1)
                lsum += __shfl_xor_sync(0xffffffffu, lsum, w);
            l_run[i] += lsum;
            // store probs transposed: Pt[j][q]
#pragma unroll
            for (int jj = 0; jj < 4; jj++)
                Pt[(tx * 4 + jj) * APAD + ty * 4 + i] = s[i][jj];
        }
        __syncthreads();

        // O += P @ V  (thread owns rows 4ty.., dims 4tx..)
#pragma unroll 8
        for (int j = 0; j < 64; j++) {
            float pa[4], va[4];
            *(float4*)pa = *(const float4*)(Pt + j * APAD + (ty << 2));
            *(float4*)va = *(const float4*)(Vs + j * APAD + (tx << 2));
#pragma unroll
            for (int i = 0; i < 4; i++)
#pragma unroll
                for (int c = 0; c < 4; c++)
                    o[i][c] = fmaf(pa[i], va[c], o[i][c]);
        }
    }

    // finalize: divide by l, write into [B,S,D] scratch
#pragma unroll
    for (int i = 0; i < 4; i++) {
        const float inv = 1.0f / l_run[i];
        const int   q   = q0 + ty * 4 + i;
        float4 res = make_float4(o[i][0] * inv, o[i][1] * inv,
                                 o[i][2] * inv, o[i][3] * inv);
        *(float4*)(g_att + ((size_t)(b * S_LEN + q)) * DMODEL + h * DK + (tx << 2)) = res;
    }
}

// ---------------------------------------------------------------------------
extern "C" void kernel_launch(void* const* d_in, const int* in_sizes, int n_in,
                              void* d_out, int out_size)
{
    (void)in_sizes; (void)n_in; (void)out_size;
    const float* q   = (const float*)d_in[0];
    const float* k   = (const float*)d_in[1];
    const float* v   = (const float*)d_in[2];
    const int*   msk = (const int*)  d_in[3];
    const float* Wq  = (const float*)d_in[4];
    const float* bq  = (const float*)d_in[5];
    const float* Wk  = (const float*)d_in[6];
    const float* bk  = (const float*)d_in[7];
    const float* Wv  = (const float*)d_in[8];
    const float* bv  = (const float*)d_in[9];
    const float* Wo  = (const float*)d_in[10];
    const float* bo  = (const float*)d_in[11];
    float* out = (float*)d_out;

    const int attn_smem = 4 * 64 * APAD * (int)sizeof(float);  // 69632 B
    cudaFuncSetAttribute(attn_kernel,
                         cudaFuncAttributeMaxDynamicSharedMemorySize, attn_smem);

    dim3 gp(DMODEL / 128, MROWS / 128, 3);
    gemm_qkv_kernel<<<gp, 256>>>(q, k, v, Wq, bq, Wk, bk, Wv, bv);

    attn_kernel<<<dim3(S_LEN / 64, B_SZ * NH), 256, attn_smem>>>(msk);

    gemm_out_kernel<<<dim3(DMODEL / 128, MROWS / 128), 256>>>(Wo, bo, out);
}